// round 11
// baseline (speedup 1.0000x reference)
#include <cuda_runtime.h>
#include <cuda_bf16.h>
#include <cstdint>
#include <cstddef>

// Problem dims (fixed by the dataset)
#define M_TOTAL 8192
#define K_DIM   4096
#define N_DIM   16384
#define TILE_M  128
#define TILE_N  128
#define TILE_K  64
#define K_ITERS (K_DIM / TILE_K)   // 64
#define N_TILES (N_DIM / TILE_N)   // 128
#define M_TILES (M_TOTAL / TILE_M) // 64
#define THREADS 128                // 4 warps: 2(M) x 2(N), 64x64 per warp
#define STAGES  3
#define NORM_SPLIT 8

#define A_STAGE (TILE_M * TILE_K * 2)            // 16384 B
#define B_STAGE (TILE_N * TILE_K * 2)            // 16384 B
#define STAGE_BYTES (A_STAGE + B_STAGE)          // 32768
#define SMEM_TOTAL_GEMM (STAGES * STAGE_BYTES)   // 98304 (x2 CTAs = 192K/SM)

// -------- static device scratch (no allocations allowed) --------
__device__ float          d_norm_part[NORM_SPLIT * N_DIM];        // split-K partial sq-sums
__device__ float          d_norm_inv[N_DIM];
__device__ __nv_bfloat16  d_gb[(size_t)M_TOTAL * K_DIM];          // g in bf16, [M,K] row-major
__device__ __nv_bfloat16  d_wt[(size_t)N_DIM * K_DIM];            // (W/norm)^T bf16, [N,K] row-major
__device__ float          d_partial[(size_t)N_TILES * M_TOTAL];   // partial LSE [n_tile][m]

// ------------------------- PTX helpers -------------------------
__device__ __forceinline__ uint32_t smem_u32(const void* p) {
    return (uint32_t)__cvta_generic_to_shared(p);
}
__device__ __forceinline__ void cp_async16(uint32_t smem, const void* gmem) {
    asm volatile("cp.async.cg.shared.global [%0], [%1], 16;" :: "r"(smem), "l"(gmem));
}
__device__ __forceinline__ void cp_commit() {
    asm volatile("cp.async.commit_group;" ::: "memory");
}
__device__ __forceinline__ void cp_wait1() {
    asm volatile("cp.async.wait_group 1;" ::: "memory");
}
__device__ __forceinline__ void ldsm_x4(uint32_t& r0, uint32_t& r1, uint32_t& r2, uint32_t& r3,
                                        uint32_t addr) {
    asm volatile("ldmatrix.sync.aligned.m8n8.x4.shared.b16 {%0,%1,%2,%3}, [%4];"
                 : "=r"(r0), "=r"(r1), "=r"(r2), "=r"(r3) : "r"(addr));
}
__device__ __forceinline__ void mma_bf16(float& d0, float& d1, float& d2, float& d3,
                                         uint32_t a0, uint32_t a1, uint32_t a2, uint32_t a3,
                                         uint32_t b0, uint32_t b1) {
    asm volatile(
        "mma.sync.aligned.m16n8k16.row.col.f32.bf16.bf16.f32 "
        "{%0,%1,%2,%3}, {%4,%5,%6,%7}, {%8,%9}, {%0,%1,%2,%3};"
        : "+f"(d0), "+f"(d1), "+f"(d2), "+f"(d3)
        : "r"(a0), "r"(a1), "r"(a2), "r"(a3), "r"(b0), "r"(b1));
}
__device__ __forceinline__ uint32_t swz(uint32_t byte_off) {
    return byte_off ^ ((byte_off >> 3) & 0x70);
}

// --------------------- prep kernels ---------------------

// 1) split-K partial column sq-sums, float4-vectorized
__global__ void norm_partial_kernel(const float4* __restrict__ W4) {
    int h4 = blockIdx.x * blockDim.x + threadIdx.x;
    int s = blockIdx.y;
    int k0 = s * (K_DIM / NORM_SPLIT);
    float4 acc = make_float4(0.f, 0.f, 0.f, 0.f);
#pragma unroll 4
    for (int k = k0; k < k0 + K_DIM / NORM_SPLIT; ++k) {
        float4 v = W4[(size_t)k * (N_DIM / 4) + h4];
        acc.x = fmaf(v.x, v.x, acc.x);
        acc.y = fmaf(v.y, v.y, acc.y);
        acc.z = fmaf(v.z, v.z, acc.z);
        acc.w = fmaf(v.w, v.w, acc.w);
    }
    reinterpret_cast<float4*>(d_norm_part)[(size_t)s * (N_DIM / 4) + h4] = acc;
}

// 1b) finalize: inv = rsqrt(sum of partials)
__global__ void norm_finalize_kernel() {
    int h = blockIdx.x * blockDim.x + threadIdx.x;
    float s = 0.f;
#pragma unroll
    for (int p = 0; p < NORM_SPLIT; ++p) s += d_norm_part[p * N_DIM + h];
    d_norm_inv[h] = rsqrtf(s);
}

// 2) Wt[h][k] = bf16(W[k][h] * norm_inv[h])  (tiled transpose)
__global__ void wt_kernel(const float* __restrict__ W) {
    __shared__ float tile[32][33];
    int h0 = blockIdx.x * 32;
    int k0 = blockIdx.y * 32;
    int tx = threadIdx.x, ty = threadIdx.y;  // (32, 8)
#pragma unroll
    for (int j = 0; j < 32; j += 8)
        tile[ty + j][tx] = W[(size_t)(k0 + ty + j) * N_DIM + h0 + tx];
    __syncthreads();
#pragma unroll
    for (int j = 0; j < 32; j += 8) {
        int h = h0 + ty + j;
        d_wt[(size_t)h * K_DIM + k0 + tx] =
            __float2bfloat16(tile[tx][ty + j] * d_norm_inv[h]);
    }
}

// 3) g -> bf16
__global__ void gb_kernel(const float4* __restrict__ g, int n4) {
    int i = blockIdx.x * blockDim.x + threadIdx.x;
    if (i >= n4) return;
    float4 v = g[i];
    __nv_bfloat162* o = reinterpret_cast<__nv_bfloat162*>(d_gb) + (size_t)i * 2;
    o[0] = __floats2bfloat162_rn(v.x, v.y);
    o[1] = __floats2bfloat162_rn(v.z, v.w);
}

// --------------------- fused GEMM + partial LSE ---------------------
// 128 threads = 4 warps in 2(M) x 2(N); each warp computes 64x64
// (4 m-tiles x 8 n-tiles). Crossbar demand 2*(1/64+1/64)*1024 = 64 B/cyc
// (half of the 32x64 config). bar.sync converges only 4 warps; the
// co-resident CTA's warps cover the convergence window.

__global__ void __launch_bounds__(THREADS, 2) gemm_lse_kernel() {
    extern __shared__ char smem[];
    const uint32_t sb = smem_u32(smem);
    const int tid = threadIdx.x;
    const int wid = tid >> 5;
    const int lane = tid & 31;
    const int mw = wid & 1;        // warp M index (0..1), 64 rows
    const int nw = wid >> 1;       // warp N index (0..1), 64 cols
    const int m0 = blockIdx.x * TILE_M;    // x = m tile (wave shares B band)
    const int n0 = blockIdx.y * TILE_N;

    const char* aBase = (const char*)d_gb + (size_t)m0 * (K_DIM * 2);
    const char* bBase = (const char*)d_wt + (size_t)n0 * (K_DIM * 2);

    auto load_stage = [&](int s, int it) {
        const uint32_t ab = sb + s * STAGE_BYTES;
        const uint32_t bb = ab + A_STAGE;
        const char* aK = aBase + it * (TILE_K * 2);
        const char* bK = bBase + it * (TILE_K * 2);
#pragma unroll
        for (int i = 0; i < A_STAGE / 16 / THREADS; ++i) {        // 8
            int idx = tid + i * THREADS;
            cp_async16(ab + swz((uint32_t)idx * 16),
                       aK + (size_t)(idx >> 3) * (K_DIM * 2) + (idx & 7) * 16);
        }
#pragma unroll
        for (int i = 0; i < B_STAGE / 16 / THREADS; ++i) {        // 8
            int idx = tid + i * THREADS;
            cp_async16(bb + swz((uint32_t)idx * 16),
                       bK + (size_t)(idx >> 3) * (K_DIM * 2) + (idx & 7) * 16);
        }
    };

    load_stage(0, 0); cp_commit();
    load_stage(1, 1); cp_commit();

    float acc[4][8][4];
#pragma unroll
    for (int t = 0; t < 4; ++t)
#pragma unroll
        for (int j = 0; j < 8; ++j)
#pragma unroll
            for (int c = 0; c < 4; ++c) acc[t][j][c] = 0.f;

    // ---- precomputed swizzled LDSM offsets; k-chunk applied via XOR ----
    const int a_row = lane & 15;
    const int a_kh  = lane >> 4;
    const int b_row = lane & 7;
    const int b_grp = (lane >> 3) & 1;
    const int b_t2  = lane >> 4;
    uint32_t a_off[4], b_off[4];
#pragma unroll
    for (int t = 0; t < 4; ++t)
        a_off[t] = swz((uint32_t)(mw * 64 + t * 16 + a_row) * 128 + a_kh * 16);
#pragma unroll
    for (int p = 0; p < 4; ++p)
        b_off[p] = swz((uint32_t)(nw * 64 + p * 16 + b_t2 * 8 + b_row) * 128 + b_grp * 16);

    for (int it = 0; it < K_ITERS; ++it) {
        cp_wait1();                 // stage `it` complete
        __syncthreads();            // cross-thread visibility + slot-reuse guard
        if (it + 2 < K_ITERS) load_stage((it + 2) % STAGES, it + 2);
        cp_commit();

        const uint32_t stageA = sb + (it % STAGES) * STAGE_BYTES;
        const uint32_t stageB = stageA + A_STAGE;

#pragma unroll
        for (int ks = 0; ks < TILE_K / 16; ++ks) {    // 4 k16 steps
            const uint32_t kx = (uint32_t)(ks * 32);
            uint32_t a[4][4];
#pragma unroll
            for (int t = 0; t < 4; ++t)
                ldsm_x4(a[t][0], a[t][1], a[t][2], a[t][3], stageA + (a_off[t] ^ kx));
            uint32_t b[8][2];
#pragma unroll
            for (int p = 0; p < 4; ++p) {
                uint32_t r0, r1, r2, r3;
                ldsm_x4(r0, r1, r2, r3, stageB + (b_off[p] ^ kx));
                b[p * 2][0] = r0; b[p * 2][1] = r1;
                b[p * 2 + 1][0] = r2; b[p * 2 + 1][1] = r3;
            }
#pragma unroll
            for (int t = 0; t < 4; ++t)
#pragma unroll
                for (int j = 0; j < 8; ++j)
                    mma_bf16(acc[t][j][0], acc[t][j][1], acc[t][j][2], acc[t][j][3],
                             a[t][0], a[t][1], a[t][2], a[t][3], b[j][0], b[j][1]);
        }
    }

    __syncthreads();   // all warps done; reuse stage smem for reduction

    // ---- fused epilogue: per-row partial logsumexp over this tile's 128 cols ----
    float2* red = (float2*)smem;   // [2 n-warps][128 rows]
#pragma unroll
    for (int t = 0; t < 4; ++t) {
#pragma unroll
        for (int half = 0; half < 2; ++half) {
            float mx = -3.4e38f;
#pragma unroll
            for (int j = 0; j < 8; ++j) {
                mx = fmaxf(mx, acc[t][j][half * 2]);
                mx = fmaxf(mx, acc[t][j][half * 2 + 1]);
            }
            mx = fmaxf(mx, __shfl_xor_sync(0xFFFFFFFF, mx, 1));
            mx = fmaxf(mx, __shfl_xor_sync(0xFFFFFFFF, mx, 2));
            float s = 0.f;
#pragma unroll
            for (int j = 0; j < 8; ++j) {
                s += __expf(acc[t][j][half * 2] - mx);
                s += __expf(acc[t][j][half * 2 + 1] - mx);
            }
            s += __shfl_xor_sync(0xFFFFFFFF, s, 1);
            s += __shfl_xor_sync(0xFFFFFFFF, s, 2);
            if ((lane & 3) == 0) {
                int row = mw * 64 + t * 16 + half * 8 + (lane >> 2);
                red[nw * 128 + row] = make_float2(mx, s);
            }
        }
    }
    __syncthreads();

    if (tid < TILE_M) {
        float2 v0 = red[tid], v1 = red[128 + tid];
        float m = fmaxf(v0.x, v1.x);
        float s = v0.y * __expf(v0.x - m) + v1.y * __expf(v1.x - m);
        d_partial[(size_t)blockIdx.y * M_TOTAL + m0 + tid] = m + __logf(s);
    }
}

// --------------------- final LSE combine ---------------------
__global__ void reduce_kernel(float* __restrict__ out) {
    int m = blockIdx.x * blockDim.x + threadIdx.x;
    if (m >= M_TOTAL) return;
    float mx = -3.4e38f;
#pragma unroll 8
    for (int j = 0; j < N_TILES; ++j)
        mx = fmaxf(mx, d_partial[(size_t)j * M_TOTAL + m]);
    float s = 0.f;
#pragma unroll 8
    for (int j = 0; j < N_TILES; ++j)
        s += __expf(d_partial[(size_t)j * M_TOTAL + m] - mx);
    out[m] = mx + logf(s);
}

// --------------------- launcher ---------------------
extern "C" void kernel_launch(void* const* d_in, const int* in_sizes, int n_in,
                              void* d_out, int out_size) {
    const float* g;
    const float* W;
    if (in_sizes[0] == M_TOTAL * K_DIM) {           // g first (expected metadata order)
        g = (const float*)d_in[0];
        W = (const float*)d_in[1];
    } else {
        g = (const float*)d_in[1];
        W = (const float*)d_in[0];
    }
    float* out = (float*)d_out;

    norm_partial_kernel<<<dim3(N_DIM / 4 / 256, NORM_SPLIT), 256>>>((const float4*)W);
    norm_finalize_kernel<<<N_DIM / 256, 256>>>();

    dim3 tb(32, 8);
    wt_kernel<<<dim3(N_DIM / 32, K_DIM / 32), tb>>>(W);

    int n4 = (M_TOTAL * K_DIM) / 4;
    gb_kernel<<<(n4 + 255) / 256, 256>>>((const float4*)g, n4);

    cudaFuncSetAttribute(gemm_lse_kernel, cudaFuncAttributeMaxDynamicSharedMemorySize,
                         SMEM_TOTAL_GEMM);
    gemm_lse_kernel<<<dim3(M_TILES, N_TILES), THREADS, SMEM_TOTAL_GEMM>>>();

    reduce_kernel<<<(M_TOTAL + 255) / 256, 256>>>(out);
}

// round 12
// speedup vs baseline: 1.0751x; 1.0751x over previous
#include <cuda_runtime.h>
#include <cuda_bf16.h>
#include <cstdint>
#include <cstddef>

// Problem dims (fixed by the dataset)
#define M_TOTAL 8192
#define K_DIM   4096
#define N_DIM   16384
#define TILE_M  128
#define TILE_N  128
#define TILE_K  64
#define K_ITERS (K_DIM / TILE_K)   // 64
#define N_TILES (N_DIM / TILE_N)   // 128
#define M_TILES (M_TOTAL / TILE_M) // 64
#define THREADS 256                // 8 warps: 4(M) x 2(N), 32x64 per warp
#define STAGES  3
#define KSLICES (K_DIM / 32)       // 128 norm partials (one per 32-row k slice)

#define A_STAGE (TILE_M * TILE_K * 2)            // 16384 B
#define B_STAGE (TILE_N * TILE_K * 2)            // 16384 B
#define STAGE_BYTES (A_STAGE + B_STAGE)          // 32768
#define SMEM_TOTAL_GEMM (STAGES * STAGE_BYTES)   // 98304 (x2 CTAs = 192K/SM)

// -------- static device scratch (no allocations allowed) --------
__device__ float          d_norm_part[(size_t)KSLICES * N_DIM];   // per-k-slice col sq-sums
__device__ float          d_norm_inv[N_DIM];
__device__ __nv_bfloat16  d_gb[(size_t)M_TOTAL * K_DIM];          // g in bf16, [M,K] row-major
__device__ __nv_bfloat16  d_wt[(size_t)N_DIM * K_DIM];            // W^T bf16 (UNnormalized), [N,K]
__device__ float          d_partial[(size_t)N_TILES * M_TOTAL];   // partial LSE [n_tile][m]

// ------------------------- PTX helpers -------------------------
__device__ __forceinline__ uint32_t smem_u32(const void* p) {
    return (uint32_t)__cvta_generic_to_shared(p);
}
__device__ __forceinline__ void cp_async16(uint32_t smem, const void* gmem) {
    asm volatile("cp.async.cg.shared.global [%0], [%1], 16;" :: "r"(smem), "l"(gmem));
}
__device__ __forceinline__ void cp_commit() {
    asm volatile("cp.async.commit_group;" ::: "memory");
}
__device__ __forceinline__ void cp_wait1() {
    asm volatile("cp.async.wait_group 1;" ::: "memory");
}
__device__ __forceinline__ void ldsm_x4(uint32_t& r0, uint32_t& r1, uint32_t& r2, uint32_t& r3,
                                        uint32_t addr) {
    asm volatile("ldmatrix.sync.aligned.m8n8.x4.shared.b16 {%0,%1,%2,%3}, [%4];"
                 : "=r"(r0), "=r"(r1), "=r"(r2), "=r"(r3) : "r"(addr));
}
__device__ __forceinline__ void mma_bf16(float& d0, float& d1, float& d2, float& d3,
                                         uint32_t a0, uint32_t a1, uint32_t a2, uint32_t a3,
                                         uint32_t b0, uint32_t b1) {
    asm volatile(
        "mma.sync.aligned.m16n8k16.row.col.f32.bf16.bf16.f32 "
        "{%0,%1,%2,%3}, {%4,%5,%6,%7}, {%8,%9}, {%0,%1,%2,%3};"
        : "+f"(d0), "+f"(d1), "+f"(d2), "+f"(d3)
        : "r"(a0), "r"(a1), "r"(a2), "r"(a3), "r"(b0), "r"(b1));
}
__device__ __forceinline__ uint32_t swz(uint32_t byte_off) {
    return byte_off ^ ((byte_off >> 3) & 0x70);
}

// --------------------- prep kernels ---------------------

// 1) FUSED: transpose W -> bf16 (unnormalized) + per-k-slice column sq-sums.
//    One 256MB pass replaces the former norm_partial + wt pair.
__global__ void wt_fused_kernel(const float* __restrict__ W) {
    __shared__ float tile[32][33];     // [k_local][h_local]
    int h0 = blockIdx.x * 32;
    int k0 = blockIdx.y * 32;
    int tx = threadIdx.x, ty = threadIdx.y;  // (32, 8)
#pragma unroll
    for (int j = 0; j < 32; j += 8)
        tile[ty + j][tx] = W[(size_t)(k0 + ty + j) * N_DIM + h0 + tx];
    __syncthreads();
    // transposed bf16 write (no normalization)
#pragma unroll
    for (int j = 0; j < 32; j += 8) {
        int h = h0 + ty + j;
        d_wt[(size_t)h * K_DIM + k0 + tx] = __float2bfloat16(tile[tx][ty + j]);
    }
    // column sq-sum partial for this 32-k slice
    int tid = ty * 32 + tx;            // 0..255
    int hl = tid >> 3;                 // 0..31
    int kc = tid & 7;                  // 0..7 (4 k each)
    float sq = 0.f;
#pragma unroll
    for (int i = 0; i < 4; ++i) {
        float v = tile[kc * 4 + i][hl];
        sq = fmaf(v, v, sq);
    }
    sq += __shfl_down_sync(0xFFFFFFFF, sq, 4);
    sq += __shfl_down_sync(0xFFFFFFFF, sq, 2);
    sq += __shfl_down_sync(0xFFFFFFFF, sq, 1);
    if (kc == 0)
        d_norm_part[(size_t)blockIdx.y * N_DIM + h0 + hl] = sq;
}

// 1b) finalize: inv = rsqrt(sum of 128 partials)
__global__ void norm_finalize_kernel() {
    int h = blockIdx.x * blockDim.x + threadIdx.x;
    float s = 0.f;
#pragma unroll 8
    for (int p = 0; p < KSLICES; ++p) s += d_norm_part[(size_t)p * N_DIM + h];
    d_norm_inv[h] = rsqrtf(s);
}

// 2) g -> bf16
__global__ void gb_kernel(const float4* __restrict__ g, int n4) {
    int i = blockIdx.x * blockDim.x + threadIdx.x;
    if (i >= n4) return;
    float4 v = g[i];
    __nv_bfloat162* o = reinterpret_cast<__nv_bfloat162*>(d_gb) + (size_t)i * 2;
    o[0] = __floats2bfloat162_rn(v.x, v.y);
    o[1] = __floats2bfloat162_rn(v.z, v.w);
}

// --------------------- fused GEMM + partial LSE ---------------------
// 256 threads = 8 warps in 4(M) x 2(N); each warp computes 32x64. 2 CTAs/SM.
// W is unnormalized in the GEMM; per-column 1/||W_col|| is applied to the
// fp32 accumulators in the epilogue (column index statically known).

__global__ void __launch_bounds__(THREADS, 2) gemm_lse_kernel() {
    extern __shared__ char smem[];
    const uint32_t sb = smem_u32(smem);
    const int tid = threadIdx.x;
    const int wid = tid >> 5;
    const int lane = tid & 31;
    const int mw = wid & 3;        // warp M index (0..3)
    const int nw = wid >> 2;       // warp N index (0..1)
    const int m0 = blockIdx.x * TILE_M;    // x = m tile (wave shares B band)
    const int n0 = blockIdx.y * TILE_N;

    const char* aBase = (const char*)d_gb + (size_t)m0 * (K_DIM * 2);
    const char* bBase = (const char*)d_wt + (size_t)n0 * (K_DIM * 2);

    auto load_stage = [&](int s, int it) {
        const uint32_t ab = sb + s * STAGE_BYTES;
        const uint32_t bb = ab + A_STAGE;
        const char* aK = aBase + it * (TILE_K * 2);
        const char* bK = bBase + it * (TILE_K * 2);
#pragma unroll
        for (int i = 0; i < A_STAGE / 16 / THREADS; ++i) {        // 4
            int idx = tid + i * THREADS;
            cp_async16(ab + swz((uint32_t)idx * 16),
                       aK + (size_t)(idx >> 3) * (K_DIM * 2) + (idx & 7) * 16);
        }
#pragma unroll
        for (int i = 0; i < B_STAGE / 16 / THREADS; ++i) {        // 4
            int idx = tid + i * THREADS;
            cp_async16(bb + swz((uint32_t)idx * 16),
                       bK + (size_t)(idx >> 3) * (K_DIM * 2) + (idx & 7) * 16);
        }
    };

    load_stage(0, 0); cp_commit();
    load_stage(1, 1); cp_commit();

    float acc[2][8][4];
#pragma unroll
    for (int t = 0; t < 2; ++t)
#pragma unroll
        for (int j = 0; j < 8; ++j)
#pragma unroll
            for (int c = 0; c < 4; ++c) acc[t][j][c] = 0.f;

    // ---- precomputed swizzled LDSM offsets; k-chunk applied via XOR ----
    const int a_row = lane & 15;
    const int a_kh  = lane >> 4;
    const int b_row = lane & 7;
    const int b_grp = (lane >> 3) & 1;
    const int b_t2  = lane >> 4;
    uint32_t a_off[2], b_off[4];
#pragma unroll
    for (int t = 0; t < 2; ++t)
        a_off[t] = swz((uint32_t)(mw * 32 + t * 16 + a_row) * 128 + a_kh * 16);
#pragma unroll
    for (int p = 0; p < 4; ++p)
        b_off[p] = swz((uint32_t)(nw * 64 + p * 16 + b_t2 * 8 + b_row) * 128 + b_grp * 16);

    for (int it = 0; it < K_ITERS; ++it) {
        cp_wait1();                 // stage `it` complete
        __syncthreads();
        if (it + 2 < K_ITERS) load_stage((it + 2) % STAGES, it + 2);
        cp_commit();

        const uint32_t stageA = sb + (it % STAGES) * STAGE_BYTES;
        const uint32_t stageB = stageA + A_STAGE;

#pragma unroll
        for (int ks = 0; ks < TILE_K / 16; ++ks) {    // 4 k16 steps
            const uint32_t kx = (uint32_t)(ks * 32);
            uint32_t a[2][4];
#pragma unroll
            for (int t = 0; t < 2; ++t)
                ldsm_x4(a[t][0], a[t][1], a[t][2], a[t][3], stageA + (a_off[t] ^ kx));
            uint32_t b[8][2];
#pragma unroll
            for (int p = 0; p < 4; ++p) {
                uint32_t r0, r1, r2, r3;
                ldsm_x4(r0, r1, r2, r3, stageB + (b_off[p] ^ kx));
                b[p * 2][0] = r0; b[p * 2][1] = r1;
                b[p * 2 + 1][0] = r2; b[p * 2 + 1][1] = r3;
            }
#pragma unroll
            for (int t = 0; t < 2; ++t)
#pragma unroll
                for (int j = 0; j < 8; ++j)
                    mma_bf16(acc[t][j][0], acc[t][j][1], acc[t][j][2], acc[t][j][3],
                             a[t][0], a[t][1], a[t][2], a[t][3], b[j][0], b[j][1]);
        }
    }

    // ---- apply column normalization to accumulators (fp32) ----
    // acc[t][j][c]: col = n0 + nw*64 + j*8 + (lane&3)*2 + (c&1)
    float ninv[8][2];
#pragma unroll
    for (int j = 0; j < 8; ++j) {
        int n = n0 + nw * 64 + j * 8 + (lane & 3) * 2;
        ninv[j][0] = d_norm_inv[n];
        ninv[j][1] = d_norm_inv[n + 1];
    }
#pragma unroll
    for (int t = 0; t < 2; ++t)
#pragma unroll
        for (int j = 0; j < 8; ++j) {
            acc[t][j][0] *= ninv[j][0];
            acc[t][j][1] *= ninv[j][1];
            acc[t][j][2] *= ninv[j][0];
            acc[t][j][3] *= ninv[j][1];
        }

    __syncthreads();   // all warps done; reuse stage smem for reduction

    // ---- fused epilogue: per-row partial logsumexp over this tile's 128 cols ----
    float2* red = (float2*)smem;   // [2 n-warps][128 rows]
#pragma unroll
    for (int t = 0; t < 2; ++t) {
#pragma unroll
        for (int half = 0; half < 2; ++half) {
            float mx = -3.4e38f;
#pragma unroll
            for (int j = 0; j < 8; ++j) {
                mx = fmaxf(mx, acc[t][j][half * 2]);
                mx = fmaxf(mx, acc[t][j][half * 2 + 1]);
            }
            mx = fmaxf(mx, __shfl_xor_sync(0xFFFFFFFF, mx, 1));
            mx = fmaxf(mx, __shfl_xor_sync(0xFFFFFFFF, mx, 2));
            float s = 0.f;
#pragma unroll
            for (int j = 0; j < 8; ++j) {
                s += __expf(acc[t][j][half * 2] - mx);
                s += __expf(acc[t][j][half * 2 + 1] - mx);
            }
            s += __shfl_xor_sync(0xFFFFFFFF, s, 1);
            s += __shfl_xor_sync(0xFFFFFFFF, s, 2);
            if ((lane & 3) == 0) {
                int row = mw * 32 + t * 16 + half * 8 + (lane >> 2);
                red[nw * 128 + row] = make_float2(mx, s);
            }
        }
    }
    __syncthreads();

    if (tid < TILE_M) {
        float2 v0 = red[tid], v1 = red[128 + tid];
        float m = fmaxf(v0.x, v1.x);
        float s = v0.y * __expf(v0.x - m) + v1.y * __expf(v1.x - m);
        d_partial[(size_t)blockIdx.y * M_TOTAL + m0 + tid] = m + __logf(s);
    }
}

// --------------------- final LSE combine ---------------------
__global__ void reduce_kernel(float* __restrict__ out) {
    int m = blockIdx.x * blockDim.x + threadIdx.x;
    if (m >= M_TOTAL) return;
    float mx = -3.4e38f;
#pragma unroll 8
    for (int j = 0; j < N_TILES; ++j)
        mx = fmaxf(mx, d_partial[(size_t)j * M_TOTAL + m]);
    float s = 0.f;
#pragma unroll 8
    for (int j = 0; j < N_TILES; ++j)
        s += __expf(d_partial[(size_t)j * M_TOTAL + m] - mx);
    out[m] = mx + logf(s);
}

// --------------------- launcher ---------------------
extern "C" void kernel_launch(void* const* d_in, const int* in_sizes, int n_in,
                              void* d_out, int out_size) {
    const float* g;
    const float* W;
    if (in_sizes[0] == M_TOTAL * K_DIM) {           // g first (expected metadata order)
        g = (const float*)d_in[0];
        W = (const float*)d_in[1];
    } else {
        g = (const float*)d_in[1];
        W = (const float*)d_in[0];
    }
    float* out = (float*)d_out;

    dim3 tb(32, 8);
    wt_fused_kernel<<<dim3(N_DIM / 32, K_DIM / 32), tb>>>(W);
    norm_finalize_kernel<<<N_DIM / 256, 256>>>();

    int n4 = (M_TOTAL * K_DIM) / 4;
    gb_kernel<<<(n4 + 255) / 256, 256>>>((const float4*)g, n4);

    cudaFuncSetAttribute(gemm_lse_kernel, cudaFuncAttributeMaxDynamicSharedMemorySize,
                         SMEM_TOTAL_GEMM);
    gemm_lse_kernel<<<dim3(M_TILES, N_TILES), THREADS, SMEM_TOTAL_GEMM>>>();

    reduce_kernel<<<(M_TOTAL + 255) / 256, 256>>>(out);
}